// round 10
// baseline (speedup 1.0000x reference)
#include <cuda_runtime.h>
#include <math.h>
#include <stdint.h>

// Problem constants (fixed by the dataset: RES=128, B=16).
#define RES    128
#define NB     16
#define NW     16                   // warps per block (one FFT per warp per stage)
#define THREADS (NW * 32)           // 512
#define NBLK   (NB * 8)             // 128 blocks = 16 clusters of 8 (one per batch)
#define NPIX   (RES * RES)
#define TWO_PI 6.2831853071795864769f

// ---- complex helpers ------------------------------------------------------
__device__ __forceinline__ float2 cadd(float2 a, float2 b) {
    return make_float2(a.x + b.x, a.y + b.y);
}
__device__ __forceinline__ float2 csub(float2 a, float2 b) {
    return make_float2(a.x - b.x, a.y - b.y);
}
__device__ __forceinline__ float2 cmul(float2 a, float2 t) {
    return make_float2(a.x * t.x - a.y * t.y, a.x * t.y + a.y * t.x);
}
// exp(+2*pi*i*k/128) via fast MUFU sincos
__device__ __forceinline__ float2 twid(int k) {
    float2 t;
    __sincosf((TWO_PI / 128.f) * (float)k, &t.y, &t.x);
    return t;
}

// shfl-exchange radix-2 DIF butterfly across lanes (distance = mask)
__device__ __forceinline__ float2 bfly_shfl(float2 v, int mask, float2 t,
                                            int lane, bool last)
{
    float2 o;
    o.x = __shfl_xor_sync(0xffffffffu, v.x, mask);
    o.y = __shfl_xor_sync(0xffffffffu, v.y, mask);
    if (lane & mask) {
        float2 d = csub(o, v);               // (lower - upper)
        return last ? d : cmul(d, t);
    }
    return cadd(v, o);
}

// ---------------------------------------------------------------------------
// 128-point radix-2 DIF FFT, sign +1 (inverse-DFT kernel), fully in
// registers.  Lane holds positions p = kk*32+lane.  On exit, position p
// holds X[bitrev7(p)].  tw[] computed once per thread, reused both stages.
// ---------------------------------------------------------------------------
__device__ __forceinline__ void fft128_reg(float2 v[4], const float2 tw[7],
                                           int lane)
{
    float2 a, b;
    a = v[0]; b = v[2]; v[0] = cadd(a, b); v[2] = cmul(csub(a, b), tw[0]);
    a = v[1]; b = v[3]; v[1] = cadd(a, b); v[3] = cmul(csub(a, b), tw[1]);
    a = v[0]; b = v[1]; v[0] = cadd(a, b); v[1] = cmul(csub(a, b), tw[2]);
    a = v[2]; b = v[3]; v[2] = cadd(a, b); v[3] = cmul(csub(a, b), tw[2]);

    #pragma unroll
    for (int kk = 0; kk < 4; ++kk) {          // 4 independent lane-chains
        v[kk] = bfly_shfl(v[kk], 16, tw[3], lane, false);
        v[kk] = bfly_shfl(v[kk],  8, tw[4], lane, false);
        v[kk] = bfly_shfl(v[kk],  4, tw[5], lane, false);
        v[kk] = bfly_shfl(v[kk],  2, tw[6], lane, false);
        v[kk] = bfly_shfl(v[kk],  1, tw[6], lane, true);   // m=1: twiddle = 1
    }
}

__device__ __forceinline__ int bitrev7(int x) {
    return (int)(__brev((unsigned)x) >> 25);
}

// ---------------------------------------------------------------------------
// Fused kernel: one 8-CTA cluster per batch.  DSMEM does the transpose.
//   Stage 1 (warp per (b,i) row): bilinear sample (general 4-tap, actual
//     traj weights), apply (-1)^(i+j), register FFT along j SHIFTED by 64
//     (slot j samples column j^64 -> output is t[w]*(-1)^w).  Each register
//     value (slot p, column w = bitrev7(p)) is stored straight into the
//     owning consumer CTA's smem tile via mapa + st.shared::cluster —
//     transpose + bit-reversal + hand-off in one instruction.
//   cluster.sync: all stage-1 DSMEM stores visible.
//   Stage 2 (warp per (b,w) column): register fill from tile row (p^64)
//     folds (-1)^h, FFT over i, bitrev scatter to staging, coalesced store
//     of both output planes.
// ---------------------------------------------------------------------------
__global__ void __launch_bounds__(THREADS) __cluster_dims__(8, 1, 1)
fused_kernel(const float* __restrict__ kin,     // [B,1,RES,RES,2]
             const float* __restrict__ traj,    // [NPIX,2]
             float* __restrict__ out)           // [B,1,2,RES,RES]
{
    __shared__ float2 tile[RES * 17];  // 17.4 KB: stage2 input tile / staging

    const int t    = threadIdx.x;
    const int u    = t >> 5;           // warp 0..15
    const int lane = t & 31;
    const int b    = blockIdx.x >> 3;  // batch == cluster index
    const int rank = blockIdx.x & 7;   // cluster rank (cluster spans 8 ctas)

    unsigned int tile_base;
    asm("{ .reg .u64 tmp; cvta.to.shared.u64 tmp, %1; cvt.u32.u64 %0, tmp; }"
        : "=r"(tile_base) : "l"(tile));

    // ---- twiddles once, reused by both FFTs ----
    float2 tw[7];
    tw[0] = twid(lane);             // m=64, pair (v0,v2)
    tw[1] = twid(32 + lane);        // m=64, pair (v1,v3)
    tw[2] = twid(2 * lane);         // m=32
    tw[3] = twid(4 * (lane & 15));  // m=16
    tw[4] = twid(8 * (lane & 7));   // m=8
    tw[5] = twid(16 * (lane & 3));  // m=4
    tw[6] = twid(32 * (lane & 1));  // m=2

    // ================= stage 1 =================
    {
        const int i = (rank << 4) + u;           // row within batch: 0..127
        const float* base = kin + b * (NPIX * 2);

        float2 v[4];
        #pragma unroll
        for (int kk = 0; kk < 4; ++kk) {
            int js = (kk * 32 + lane) ^ 64;      // shifted sample: folds (-1)^w
            int m  = i * RES + js;
            float2 tj = *(const float2*)&traj[2 * m];
            float pr = tj.x + 0.5f * RES;
            float pc = tj.y + 0.5f * RES;
            float r0f = floorf(pr), c0f = floorf(pc);
            float wr = pr - r0f, wc = pc - c0f;
            int r0 = min(max((int)r0f, 0), RES - 1);
            int r1 = min(r0 + 1, RES - 1);
            int c0 = min(max((int)c0f, 0), RES - 1);
            int c1 = min(c0 + 1, RES - 1);
            float2 v00 = *(const float2*)(base + (r0 * RES + c0) * 2);
            float2 v01 = *(const float2*)(base + (r0 * RES + c1) * 2);
            float2 v10 = *(const float2*)(base + (r1 * RES + c0) * 2);
            float2 v11 = *(const float2*)(base + (r1 * RES + c1) * 2);
            float w00 = (1.f - wr) * (1.f - wc);
            float w01 = (1.f - wr) * wc;
            float w10 = wr * (1.f - wc);
            float w11 = wr * wc;
            float sx = w00 * v00.x + w01 * v01.x + w10 * v10.x + w11 * v11.x;
            float sy = w00 * v00.y + w01 * v01.y + w10 * v10.y + w11 * v11.y;
            float sgn = ((i + js) & 1) ? -1.f : 1.f;
            v[kk] = make_float2(sgn * sx, sgn * sy);
        }

        fft128_reg(v, tw, lane);

        // DSMEM scatter: slot p holds t'[i][w], w = bitrev7(p).
        // Target CTA = w>>4 owns columns [16*(w>>4), +16); slot = w&15.
        #pragma unroll
        for (int kk = 0; kk < 4; ++kk) {
            int w    = bitrev7(kk * 32 + lane);
            int tgt  = w >> 4;
            unsigned int laddr =
                tile_base + (unsigned int)(i * 17 + (w & 15)) * 8u;
            unsigned long long vv = *(unsigned long long*)&v[kk];
            asm volatile(
                "{ .reg .b32 ra;\n\t"
                "  mapa.shared::cluster.u32 ra, %0, %1;\n\t"
                "  st.shared::cluster.b64 [ra], %2; }"
                :: "r"(laddr), "r"(tgt), "l"(vv) : "memory");
        }
    }

    // ================= cluster barrier =================
    asm volatile("barrier.cluster.arrive.aligned;" ::: "memory");
    asm volatile("barrier.cluster.wait.aligned;"   ::: "memory");

    // ================= stage 2 =================
    {
        const int w0 = rank * 16;                // this CTA's 16 output columns

        // register fill from tile row (p^64): folds (-1)^h (<=2-way, pad 17)
        float2 v[4];
        #pragma unroll
        for (int kk = 0; kk < 4; ++kk)
            v[kk] = tile[((kk * 32 + lane) ^ 64) * 17 + u];
        __syncthreads();   // all reads done before tile reused as staging

        fft128_reg(v, tw, lane);

        // bitrev scatter into staging (no sign needed), slot-swizzled <=2-way
        #pragma unroll
        for (int kk = 0; kk < 4; ++kk) {
            int h = bitrev7(kk * 32 + lane);
            tile[h * 17 + ((u + (h >> 2)) & 15)] = v[kk];
        }
        __syncthreads();

        // block-coalesced output store: both planes
        float* ob = out + b * (2 * NPIX);
        #pragma unroll
        for (int r = 0; r < 4; ++r) {
            int idx = r * THREADS + t;           // 0..2047
            int h = idx >> 4, dw = idx & 15;
            float2 r2 = tile[h * 17 + ((dw + (h >> 2)) & 15)];
            ob[h * RES + w0 + dw]        = r2.x;   // real plane
            ob[NPIX + h * RES + w0 + dw] = r2.y;   // imag plane
        }
    }
}

// ---------------------------------------------------------------------------
extern "C" void kernel_launch(void* const* d_in, const int* in_sizes, int n_in,
                              void* d_out, int out_size)
{
    const float* kin  = (const float*)d_in[0];
    const float* traj = (const float*)d_in[1];
    // Defensive: metadata order is (k_space [524288], trajectory [32768]).
    if (n_in >= 2 && in_sizes[0] == 2 * NPIX) {
        kin  = (const float*)d_in[1];
        traj = (const float*)d_in[0];
    }
    float* out = (float*)d_out;

    fused_kernel<<<NBLK, THREADS>>>(kin, traj, out);
    (void)out_size;
}

// round 11
// speedup vs baseline: 1.2063x; 1.2063x over previous
#include <cuda_runtime.h>
#include <math.h>
#include <stdint.h>

// Problem constants (fixed by the dataset: RES=128, B=16).
#define RES    128
#define NB     16
#define NW     16                   // warps per block (one FFT per warp per stage)
#define THREADS (NW * 32)           // 512
#define NBLK   ((NB * RES) / NW)    // 128 blocks -> 1 per SM, all co-resident
#define BPB    8                    // blocks per batch (barrier domain)
#define NPIX   (RES * RES)
#define TWO_PI 6.2831853071795864769f

// Scratch (no runtime allocation allowed).
__device__ float2   g_t[NB * NPIX];        // t'[b][i][w], 2 MB
__device__ unsigned g_count[NB * 32];      // per-batch barrier counters (1 line apart)

// ---- complex helpers ------------------------------------------------------
__device__ __forceinline__ float2 cadd(float2 a, float2 b) {
    return make_float2(a.x + b.x, a.y + b.y);
}
__device__ __forceinline__ float2 csub(float2 a, float2 b) {
    return make_float2(a.x - b.x, a.y - b.y);
}
__device__ __forceinline__ float2 cmul(float2 a, float2 t) {
    return make_float2(a.x * t.x - a.y * t.y, a.x * t.y + a.y * t.x);
}
__device__ __forceinline__ float2 shfl2(float2 v, int src) {
    float2 o;
    o.x = __shfl_sync(0xffffffffu, v.x, src);
    o.y = __shfl_sync(0xffffffffu, v.y, src);
    return o;
}

// shfl-exchange radix-2 DIF butterfly across lanes (distance = mask)
__device__ __forceinline__ float2 bfly_shfl(float2 v, int mask, float2 t,
                                            int lane, bool last)
{
    float2 o;
    o.x = __shfl_xor_sync(0xffffffffu, v.x, mask);
    o.y = __shfl_xor_sync(0xffffffffu, v.y, mask);
    if (lane & mask) {
        float2 d = csub(o, v);               // (lower - upper)
        return last ? d : cmul(d, t);
    }
    return cadd(v, o);
}

// ---------------------------------------------------------------------------
// 128-point radix-2 DIF FFT, sign +1 (inverse-DFT kernel), fully in
// registers.  Lane holds positions p = kk*32+lane.  On exit, position p
// holds X[bitrev7(p)].  tw[] computed once per thread, reused both stages.
// ---------------------------------------------------------------------------
__device__ __forceinline__ void fft128_reg(float2 v[4], const float2 tw[7],
                                           int lane)
{
    float2 a, b;
    a = v[0]; b = v[2]; v[0] = cadd(a, b); v[2] = cmul(csub(a, b), tw[0]);
    a = v[1]; b = v[3]; v[1] = cadd(a, b); v[3] = cmul(csub(a, b), tw[1]);
    a = v[0]; b = v[1]; v[0] = cadd(a, b); v[1] = cmul(csub(a, b), tw[2]);
    a = v[2]; b = v[3]; v[2] = cadd(a, b); v[3] = cmul(csub(a, b), tw[2]);

    #pragma unroll
    for (int kk = 0; kk < 4; ++kk) {          // 4 independent lane-chains
        v[kk] = bfly_shfl(v[kk], 16, tw[3], lane, false);
        v[kk] = bfly_shfl(v[kk],  8, tw[4], lane, false);
        v[kk] = bfly_shfl(v[kk],  4, tw[5], lane, false);
        v[kk] = bfly_shfl(v[kk],  2, tw[6], lane, false);
        v[kk] = bfly_shfl(v[kk],  1, tw[6], lane, true);   // m=1: twiddle = 1
    }
}

__device__ __forceinline__ int bitrev7(int x) {
    return (int)(__brev((unsigned)x) >> 25);
}
// 2-way-max bank swizzle for stage-1 bitrev scatter (8 B accesses)
__device__ __forceinline__ int swz(int x) { return x ^ ((x >> 4) & 7); }

// ---------------------------------------------------------------------------
// Fused kernel, per-batch barrier (best-known hand-off: L2 via g_t).
//   Twiddles: tw0 = exp(i*pi*lane/64) from 2 MUFU ops; the rest derived
//   algebraically (i*tw0, tw0^2) and by the shfl identity
//   tw[k+1](lane) = tw[k]((2*lane)&31)  (angle doubling, exact mod 128).
// ---------------------------------------------------------------------------
__global__ void __launch_bounds__(THREADS, 1) fused_kernel(
    const float* __restrict__ kin,     // [B,1,RES,RES,2]
    const float* __restrict__ traj,    // [NPIX,2]
    float* __restrict__ out)           // [B,1,2,RES,RES]
{
    __shared__ float2 sbuf[RES * 17];  // 17.4 KB: stage1 rows / stage2 tile+staging

    const int t    = threadIdx.x;
    const int u    = t >> 5;           // warp 0..15
    const int lane = t & 31;
    const int b    = blockIdx.x >> 3;  // batch (8 blocks per batch)

    // ---- twiddles: 2 MUFU + algebra + shfl chain ----
    float2 tw[7];
    __sincosf((TWO_PI / 128.f) * (float)lane, &tw[0].y, &tw[0].x);  // twid(lane)
    tw[1] = make_float2(-tw[0].y, tw[0].x);                // twid(32+lane) = i*tw0
    tw[2] = cmul(tw[0], tw[0]);                            // twid(2*lane) (exact)
    {
        int src = (2 * lane) & 31;                         // angle-doubling source
        tw[3] = shfl2(tw[2], src);                         // twid(4*(lane&15))
        tw[4] = shfl2(tw[3], src);                         // twid(8*(lane&7))
        tw[5] = shfl2(tw[4], src);                         // twid(16*(lane&3))
        tw[6] = shfl2(tw[5], src);                         // twid(32*(lane&1))
    }

    // ================= stage 1 =================
    {
        const int i = ((blockIdx.x & 7) << 4) + u;   // row within batch
        const float* base = kin + b * (NPIX * 2);

        float2 v[4];
        #pragma unroll
        for (int kk = 0; kk < 4; ++kk) {
            int js = (kk * 32 + lane) ^ 64;   // shifted sample: folds (-1)^w
            int m  = i * RES + js;
            float2 tj = *(const float2*)&traj[2 * m];
            float pr = tj.x + 0.5f * RES;
            float pc = tj.y + 0.5f * RES;
            float r0f = floorf(pr), c0f = floorf(pc);
            float wr = pr - r0f, wc = pc - c0f;
            int r0 = min(max((int)r0f, 0), RES - 1);
            int r1 = min(r0 + 1, RES - 1);
            int c0 = min(max((int)c0f, 0), RES - 1);
            int c1 = min(c0 + 1, RES - 1);
            float2 v00 = *(const float2*)(base + (r0 * RES + c0) * 2);
            float2 v01 = *(const float2*)(base + (r0 * RES + c1) * 2);
            float2 v10 = *(const float2*)(base + (r1 * RES + c0) * 2);
            float2 v11 = *(const float2*)(base + (r1 * RES + c1) * 2);
            float w00 = (1.f - wr) * (1.f - wc);
            float w01 = (1.f - wr) * wc;
            float w10 = wr * (1.f - wc);
            float w11 = wr * wc;
            float sx = w00 * v00.x + w01 * v01.x + w10 * v10.x + w11 * v11.x;
            float sy = w00 * v00.y + w01 * v01.y + w10 * v10.y + w11 * v11.y;
            float sgn = ((i + js) & 1) ? -1.f : 1.f;
            v[kk] = make_float2(sgn * sx, sgn * sy);
        }

        fft128_reg(v, tw, lane);

        // bit-reversal scatter (warp-private smem region, swizzled <=2-way)
        float2* srow = sbuf + u * RES;
        #pragma unroll
        for (int kk = 0; kk < 4; ++kk)
            srow[swz(bitrev7(kk * 32 + lane))] = v[kk];
        __syncwarp();
        float2* tp = g_t + (b * RES + i) * RES;
        #pragma unroll
        for (int k = 0; k < 4; ++k) {
            int w = k * 32 + lane;
            tp[w] = srow[swz(w)];
        }
    }

    // ================= per-batch barrier =================
    __threadfence();                          // release g_t writes
    __syncthreads();                          // whole block arrived
    if (t == 0) {
        unsigned* cnt = &g_count[b * 32];
        unsigned a = atomicAdd(cnt, 1u);
        unsigned target = a - (a & (BPB - 1u)) + BPB;   // per-launch release
        while (*(volatile unsigned*)cnt < target)
            __nanosleep(20);
        __threadfence();                      // acquire
    }
    __syncthreads();

    // ================= stage 2 =================
    {
        const int w0 = (blockIdx.x & 7) * 16;    // 16 columns per block

        // block-coalesced tile load: 128 i x 16 w (128 B per row segment)
        const float2* __restrict__ tb = g_t + b * NPIX + w0;
        #pragma unroll
        for (int r = 0; r < 4; ++r) {
            int idx = r * THREADS + t;           // 0..2047
            int i = idx >> 4, dw = idx & 15;
            sbuf[i * 17 + dw] = tb[i * RES + dw];
        }
        __syncthreads();

        // register fill from row (p^64): folds (-1)^h (<=2-way, pad 17)
        float2 v[4];
        #pragma unroll
        for (int kk = 0; kk < 4; ++kk)
            v[kk] = sbuf[((kk * 32 + lane) ^ 64) * 17 + u];
        __syncthreads();   // all reads done before sbuf reused as staging

        fft128_reg(v, tw, lane);

        // bitrev scatter into staging (no sign needed), slot-swizzled <=2-way
        #pragma unroll
        for (int kk = 0; kk < 4; ++kk) {
            int h = bitrev7(kk * 32 + lane);
            sbuf[h * 17 + ((u + (h >> 2)) & 15)] = v[kk];
        }
        __syncthreads();

        // block-coalesced output store: both planes
        float* ob = out + b * (2 * NPIX);
        #pragma unroll
        for (int r = 0; r < 4; ++r) {
            int idx = r * THREADS + t;
            int h = idx >> 4, dw = idx & 15;
            float2 r2 = sbuf[h * 17 + ((dw + (h >> 2)) & 15)];
            ob[h * RES + w0 + dw]        = r2.x;   // real plane
            ob[NPIX + h * RES + w0 + dw] = r2.y;   // imag plane
        }
    }
}

// ---------------------------------------------------------------------------
extern "C" void kernel_launch(void* const* d_in, const int* in_sizes, int n_in,
                              void* d_out, int out_size)
{
    const float* kin  = (const float*)d_in[0];
    const float* traj = (const float*)d_in[1];
    // Defensive: metadata order is (k_space [524288], trajectory [32768]).
    if (n_in >= 2 && in_sizes[0] == 2 * NPIX) {
        kin  = (const float*)d_in[1];
        traj = (const float*)d_in[0];
    }
    float* out = (float*)d_out;

    fused_kernel<<<NBLK, THREADS>>>(kin, traj, out);
    (void)out_size;
}